// round 9
// baseline (speedup 1.0000x reference)
#include <cuda_runtime.h>
#include <cstdint>

// ---------------------------------------------------------------------------
// B-spline basis (cubic, DF=16) via de Boor's algorithm.
// KNOTS = [0,0,0] ++ linspace(0, 1+1e-7, 14) ++ [1,1,1]   (fp32, numpy-exact)
// vs R5/R8: single-barrier software pipeline. Dense stride-16 double buffer
// (smem layout == output layout). Per tile: compute (regs) -> prefetch next t
// -> ONE sync -> scatter into buf P -> copy-out buf Q (prev tile) via
// LDS.128/STG.128. Produce/consume hit different buffers between the same
// barriers, so one sync per tile is sufficient; copy-out latency hides under
// the next tile's compute. Persistent residency-sized grid (148x6).
// ---------------------------------------------------------------------------

#define STEP_D (1.0000001 / 13.0)
#define KP(i)  ((float)((double)(i) * STEP_D))

__constant__ float KN[20] = {
    0.0f, 0.0f, 0.0f,
    0.0f,                                   // KN[3]  = linspace[0]
    KP(1),  KP(2),  KP(3),  KP(4),  KP(5),  KP(6),
    KP(7),  KP(8),  KP(9),  KP(10), KP(11), KP(12),
    (float)1.0000001,                       // KN[16] = linspace endpoint (exact stop)
    1.0f, 1.0f, 1.0f
};

#define INV_H ((float)(13.0 / 1.0000001))

#define TPB   256
#define BUFW  (TPB * 16)            // floats per buffer (dense: stride 16)
#define NSM   148
#define CPSM  6                     // 2 x 16KB buffers -> 6 CTAs/SM

__global__ __launch_bounds__(TPB) void bspline_kernel(
    const float* __restrict__ ts,
    float* __restrict__ outf,
    int n)
{
    __shared__ float sKN[20];
    __shared__ __align__(128) float sB[2][BUFW];

    const int tid = threadIdx.x;
    const int G   = gridDim.x;
    const int nt  = (n + TPB - 1) / TPB;     // 256-element tiles

    if (tid < 20) sKN[tid] = KN[tid];

    // Zero this thread's row in both buffers.
    {
        float4 z = make_float4(0.f, 0.f, 0.f, 0.f);
        #pragma unroll
        for (int b = 0; b < 2; b++) {
            float4* r = (float4*)(sB[b] + tid * 16);
            #pragma unroll
            for (int i = 0; i < 4; i++) r[i] = z;
        }
    }
    int pj[2] = {0, 0};

    int tile = blockIdx.x;
    float t = 0.0f;
    if (tile < nt) {
        long long gi = (long long)tile * TPB + tid;
        t = ts[(gi < n) ? gi : (n - 1)];
    }

    __syncthreads();   // knots + zero-fill visible

    const long long limit4 = (long long)n * 4;
    int parity = 0;
    long long prev_tl = -1;      // tile sitting in buf[parity^1], not yet stored

    #pragma unroll 1
    for (; tile < nt; tile += G, parity ^= 1) {
        // ---- de Boor (registers only): 4 nonzero basis, span j in [0,12] ----
        int j = (int)(t * INV_H);
        j = max(0, min(12, j));
        j -= (j > 0)  && (t <  sKN[3 + j]);
        j += (j < 12) && (t >= sKN[4 + j]);

        const int span = j + 3;
        const float l1 = t - sKN[span];
        const float l2 = t - sKN[span - 1];
        const float l3 = t - sKN[span - 2];
        const float r1 = sKN[span + 1] - t;
        const float r2 = sKN[span + 2] - t;
        const float r3 = sKN[span + 3] - t;

        float N0 = 1.0f, N1, N2, N3, sv, tp;
        tp = __fdividef(N0, r1 + l1); N0 = r1 * tp; N1 = l1 * tp;
        tp = __fdividef(N0, r1 + l2); N0 = r1 * tp; sv = l2 * tp;
        tp = __fdividef(N1, r2 + l1); N1 = sv + r2 * tp; N2 = l1 * tp;
        tp = __fdividef(N0, r1 + l3); N0 = r1 * tp; sv = l3 * tp;
        tp = __fdividef(N1, r2 + l2); N1 = sv + r2 * tp; sv = l2 * tp;
        tp = __fdividef(N2, r3 + l1); N2 = sv + r3 * tp; N3 = l1 * tp;

        // Prefetch next tile's t.
        float tn = 0.0f;
        if (tile + G < nt) {
            long long gn = (long long)(tile + G) * TPB + tid;
            tn = ts[(gn < n) ? gn : (n - 1)];
        }

        __syncthreads();   // prev consume done; prev scatter visible

        // Produce: rezero old cells + scatter 4 nonzeros into buf[parity].
        {
            float* row = sB[parity] + tid * 16;
            const int q = pj[parity];
            row[q] = 0.f; row[q + 1] = 0.f; row[q + 2] = 0.f; row[q + 3] = 0.f;
            row[j] = N0; row[j + 1] = N1; row[j + 2] = N2; row[j + 3] = N3;
            pj[parity] = j;
        }

        // Consume: store the tile scattered last iteration (buf[parity^1]).
        if (prev_tl >= 0) {
            const float* buf = sB[parity ^ 1];
            const long long obase = prev_tl * (TPB * 4);   // float4 units
            float4* ob = (float4*)outf + obase;
            #pragma unroll
            for (int i = 0; i < 4; i++) {
                int f = tid + TPB * i;
                if (obase + f < limit4)
                    ob[f] = ((const float4*)buf)[f];
            }
        }

        prev_tl = tile;
        t = tn;
    }

    // Drain: store the final produced tile.
    __syncthreads();
    if (prev_tl >= 0) {
        const float* buf = sB[parity ^ 1];
        const long long obase = prev_tl * (TPB * 4);
        float4* ob = (float4*)outf + obase;
        #pragma unroll
        for (int i = 0; i < 4; i++) {
            int f = tid + TPB * i;
            if (obase + f < limit4)
                ob[f] = ((const float4*)buf)[f];
        }
    }
}

extern "C" void kernel_launch(void* const* d_in, const int* in_sizes, int n_in,
                              void* d_out, int out_size)
{
    const float* ts = (const float*)d_in[0];
    float* outf = (float*)d_out;
    const int n = in_sizes[0];           // 32 * 131072 = 4194304 elements
    const int nt = (n + TPB - 1) / TPB;  // 16384 tiles
    int blocks = NSM * CPSM;             // 888 persistent CTAs
    if (blocks > nt) blocks = nt;
    bspline_kernel<<<blocks, TPB>>>(ts, outf, n);
}

// round 10
// speedup vs baseline: 1.2757x; 1.2757x over previous
#include <cuda_runtime.h>
#include <cstdint>

// ---------------------------------------------------------------------------
// B-spline basis (cubic, DF=16) via de Boor's algorithm.
// KNOTS = [0,0,0] ++ linspace(0, 1+1e-7, 14) ++ [1,1,1]   (fp32, numpy-exact)
// vs R5 (best, 51.7us): warp-autonomous tiles. Each warp owns 32 consecutive
// elements per tile with a private 32x20 smem slab, so the two block-wide
// __syncthreads per tile become __syncwarp (no cross-warp jitter coupling,
// no BAR cost). Copy-out uses __stcs streaming stores (output is write-once,
// never re-read: don't let 256MB of dead lines churn L2).
// ---------------------------------------------------------------------------

#define STEP_D (1.0000001 / 13.0)
#define KP(i)  ((float)((double)(i) * STEP_D))

__constant__ float KN[20] = {
    0.0f, 0.0f, 0.0f,
    0.0f,                                   // KN[3]  = linspace[0]
    KP(1),  KP(2),  KP(3),  KP(4),  KP(5),  KP(6),
    KP(7),  KP(8),  KP(9),  KP(10), KP(11), KP(12),
    (float)1.0000001,                       // KN[16] = linspace endpoint (exact stop)
    1.0f, 1.0f, 1.0f
};

#define INV_H ((float)(13.0 / 1.0000001))

#define TPB   256
#define NW    (TPB / 32)
#define TILES 8                 // elements per block = 2048
#define RSTR  20                // padded row stride (16 data + 4 pad floats)

__global__ __launch_bounds__(TPB) void bspline_kernel(
    const float* __restrict__ ts,
    float4* __restrict__ out4,
    int n)
{
    __shared__ float sKN[20];
    __shared__ float sT[NW][32 * RSTR];     // 2.5KB per warp slab

    const int tid  = threadIdx.x;
    const int wid  = tid >> 5;
    const int lane = tid & 31;

    if (tid < 20) sKN[tid] = KN[tid];

    float* wbuf = sT[wid];

    // Pre-zero this thread's row (16 data cols) in its warp slab.
    {
        float4 z = make_float4(0.f, 0.f, 0.f, 0.f);
        float4* r = (float4*)(wbuf + lane * RSTR);
        r[0] = z; r[1] = z; r[2] = z; r[3] = z;
    }
    int pj = 0;

    const long long base = (long long)blockIdx.x * (TPB * TILES);
    const long long limit4 = (long long)n * 4;

    // Warp w's element for tile k: base + k*TPB + wid*32 + lane.
    long long egi = base + (wid << 5) + lane;
    float t = ts[(egi < n) ? egi : (n - 1)];

    __syncthreads();   // knots visible to all warps (only block-wide sync)

    #pragma unroll 1
    for (int k = 0; k < TILES; k++) {
        // ---- de Boor: 4 nonzero cubic basis functions, span j in [0,12] ----
        int j = (int)(t * INV_H);
        j = max(0, min(12, j));
        j -= (j > 0)  && (t <  sKN[3 + j]);
        j += (j < 12) && (t >= sKN[4 + j]);

        const int span = j + 3;
        const float l1 = t - sKN[span];
        const float l2 = t - sKN[span - 1];
        const float l3 = t - sKN[span - 2];
        const float r1 = sKN[span + 1] - t;
        const float r2 = sKN[span + 2] - t;
        const float r3 = sKN[span + 3] - t;

        float N0 = 1.0f, N1, N2, N3, sv, tp;
        tp = __fdividef(N0, r1 + l1); N0 = r1 * tp; N1 = l1 * tp;
        tp = __fdividef(N0, r1 + l2); N0 = r1 * tp; sv = l2 * tp;
        tp = __fdividef(N1, r2 + l1); N1 = sv + r2 * tp; N2 = l1 * tp;
        tp = __fdividef(N0, r1 + l3); N0 = r1 * tp; sv = l3 * tp;
        tp = __fdividef(N1, r2 + l2); N1 = sv + r2 * tp; sv = l2 * tp;
        tp = __fdividef(N2, r3 + l1); N2 = sv + r3 * tp; N3 = l1 * tp;

        // Prefetch next tile's t (hides under scatter + copy-out).
        float tn = 0.0f;
        if (k + 1 < TILES) {
            long long gn = egi + (long long)(k + 1) * TPB;
            tn = ts[(gn < n) ? gn : (n - 1)];
        }

        // Re-zero previous cells, scatter the 4 new nonzeros.
        float* row = wbuf + lane * RSTR;
        row[pj] = 0.f; row[pj + 1] = 0.f; row[pj + 2] = 0.f; row[pj + 3] = 0.f;
        row[j] = N0; row[j + 1] = N1; row[j + 2] = N2; row[j + 3] = N3;
        pj = j;

        __syncwarp();

        // Copy-out: warp's 32 elements -> 128 contiguous float4s, streaming.
        const long long tbase = base + (long long)k * TPB + (wid << 5);
        float4* ob = out4 + tbase * 4;
        #pragma unroll
        for (int i = 0; i < 4; i++) {
            const int f = lane + 32 * i;
            const float4 v = *(const float4*)(wbuf + (f >> 2) * RSTR + (f & 3) * 4);
            if (tbase * 4 + f < limit4)
                __stcs(&ob[f], v);
        }

        __syncwarp();   // slab reads done before next tile's scatter

        t = tn;
    }
}

extern "C" void kernel_launch(void* const* d_in, const int* in_sizes, int n_in,
                              void* d_out, int out_size)
{
    const float* ts = (const float*)d_in[0];
    float4* out4 = (float4*)d_out;
    const int n = in_sizes[0];           // 32 * 131072 = 4194304 elements
    const int epb = TPB * TILES;
    const int blocks = (n + epb - 1) / epb;
    bspline_kernel<<<blocks, TPB>>>(ts, out4, n);
}

// round 11
// speedup vs baseline: 1.3620x; 1.0677x over previous
#include <cuda_runtime.h>
#include <cstdint>

// ---------------------------------------------------------------------------
// B-spline basis (cubic, DF=16) via de Boor's algorithm.
// KNOTS = [0,0,0] ++ linspace(0, 1+1e-7, 14) ++ [1,1,1]   (fp32, numpy-exact)
// vs R10 (best): dense stride-16 smem tile (== output layout) with per-element
// slot rotation r(e)=(e>>1)&3 -> BOTH the 4x STS.128 scatter and the 4x
// LDS.128 copy-out are bank-conflict-free (stride-20 cost 2-way on every
// LDS.128). Writer builds all 4 slots via selects (no re-zero state). Warp-
// autonomous tiles, __syncwarp only, __stcs streaming stores.
// ---------------------------------------------------------------------------

#define STEP_D (1.0000001 / 13.0)
#define KP(i)  ((float)((double)(i) * STEP_D))

__constant__ float KN[20] = {
    0.0f, 0.0f, 0.0f,
    0.0f,                                   // KN[3]  = linspace[0]
    KP(1),  KP(2),  KP(3),  KP(4),  KP(5),  KP(6),
    KP(7),  KP(8),  KP(9),  KP(10), KP(11), KP(12),
    (float)1.0000001,                       // KN[16] = linspace endpoint (exact stop)
    1.0f, 1.0f, 1.0f
};

#define INV_H ((float)(13.0 / 1.0000001))

#define TPB   256
#define NW    (TPB / 32)
#define TILES 8                 // elements per block = 2048

__global__ __launch_bounds__(TPB) void bspline_kernel(
    const float* __restrict__ ts,
    float4* __restrict__ out4,
    int n)
{
    __shared__ float sKN[20];
    __shared__ __align__(128) float4 sT[NW][32 * 4];   // dense 2KB per warp slab

    const int tid  = threadIdx.x;
    const int wid  = tid >> 5;
    const int lane = tid & 31;

    if (tid < 20) sKN[tid] = KN[tid];

    float4* wbuf = sT[wid];
    const int rot = (lane >> 1) & 3;        // this thread's element rotation

    const long long base   = (long long)blockIdx.x * (TPB * TILES);
    const long long limit4 = (long long)n * 4;

    // Warp w's element for tile k: base + k*TPB + wid*32 + lane.
    long long egi = base + (wid << 5) + lane;
    float t = ts[(egi < n) ? egi : (n - 1)];

    __syncthreads();   // knots visible (only block-wide sync)

    #pragma unroll 1
    for (int k = 0; k < TILES; k++) {
        // ---- de Boor: 4 nonzero cubic basis functions, span j in [0,12] ----
        int j = (int)(t * INV_H);
        j = max(0, min(12, j));
        j -= (j > 0)  && (t <  sKN[3 + j]);
        j += (j < 12) && (t >= sKN[4 + j]);

        const int span = j + 3;
        const float l1 = t - sKN[span];
        const float l2 = t - sKN[span - 1];
        const float l3 = t - sKN[span - 2];
        const float r1 = sKN[span + 1] - t;
        const float r2 = sKN[span + 2] - t;
        const float r3 = sKN[span + 3] - t;

        float N0 = 1.0f, N1, N2, N3, sv, tp;
        tp = __fdividef(N0, r1 + l1); N0 = r1 * tp; N1 = l1 * tp;
        tp = __fdividef(N0, r1 + l2); N0 = r1 * tp; sv = l2 * tp;
        tp = __fdividef(N1, r2 + l1); N1 = sv + r2 * tp; N2 = l1 * tp;
        tp = __fdividef(N0, r1 + l3); N0 = r1 * tp; sv = l3 * tp;
        tp = __fdividef(N1, r2 + l2); N1 = sv + r2 * tp; sv = l2 * tp;
        tp = __fdividef(N2, r3 + l1); N2 = sv + r3 * tp; N3 = l1 * tp;

        // Prefetch next tile's t.
        float tn = 0.0f;
        if (k + 1 < TILES) {
            long long gn = egi + (long long)(k + 1) * TPB;
            tn = ts[(gn < n) ? gn : (n - 1)];
        }

        // ---- Build the element's 16-float row as 4 float4 slots ----
        const int jq  = j >> 2;
        const int jr  = j & 3;
        const int jq1 = (jq + 1) & 3;
        // vA = row slot jq (N shifted right by jr), vB = row slot jq+1.
        const float vA0 = (jr == 0) ? N0 : 0.f;
        const float vA1 = (jr == 0) ? N1 : (jr == 1) ? N0 : 0.f;
        const float vA2 = (jr == 0) ? N2 : (jr == 1) ? N1 : (jr == 2) ? N0 : 0.f;
        const float vA3 = (jr == 0) ? N3 : (jr == 1) ? N2 : (jr == 2) ? N1 : N0;
        const float vB0 = (jr == 1) ? N3 : (jr == 2) ? N2 : (jr == 3) ? N1 : 0.f;
        const float vB1 = (jr == 2) ? N3 : (jr == 3) ? N2 : 0.f;
        const float vB2 = (jr == 3) ? N3 : 0.f;

        // Scatter: logical slot s -> physical slot (s+rot)&3. Conflict-free.
        float4* erow = wbuf + (lane << 2);
        #pragma unroll
        for (int s = 0; s < 4; s++) {
            const bool a = (s == jq);
            const bool b = (s == jq1);
            float4 v;
            v.x = a ? vA0 : b ? vB0 : 0.f;
            v.y = a ? vA1 : b ? vB1 : 0.f;
            v.z = a ? vA2 : b ? vB2 : 0.f;
            v.w = a ? vA3 : 0.f;            // vB3 == 0
            erow[(s + rot) & 3] = v;
        }

        __syncwarp();

        // ---- Copy-out: 128 contiguous float4s, CF LDS.128 + streaming STG ----
        const long long tbase = base + (long long)k * TPB + (wid << 5);
        float4* ob = out4 + tbase * 4;
        #pragma unroll
        for (int i = 0; i < 4; i++) {
            const int f  = lane + 32 * i;
            const int e  = f >> 2;
            const int c  = f & 3;
            const int re = (e >> 1) & 3;
            const float4 v = wbuf[(e << 2) + ((c + re) & 3)];
            if (tbase * 4 + f < limit4)
                __stcs(&ob[f], v);
        }

        __syncwarp();   // slab reads done before next tile's scatter

        t = tn;
    }
}

extern "C" void kernel_launch(void* const* d_in, const int* in_sizes, int n_in,
                              void* d_out, int out_size)
{
    const float* ts = (const float*)d_in[0];
    float4* out4 = (float4*)d_out;
    const int n = in_sizes[0];           // 32 * 131072 = 4194304 elements
    const int epb = TPB * TILES;
    const int blocks = (n + epb - 1) / epb;
    bspline_kernel<<<blocks, TPB>>>(ts, out4, n);
}